// round 2
// baseline (speedup 1.0000x reference)
#include <cuda_runtime.h>
#include <math.h>

// Problem constants
#define S_LEN 2048
#define B_SZ  2
#define H_DIM 2048
#define NH    16
#define DH    128
#define N3    (3 * H_DIM)          // 6144
#define M_ROWS (S_LEN * B_SZ)      // 4096
#define MASK_VALUE (-10000.0f)

// Scratch (no cudaMalloc allowed) — [b][h][s][d] layout for q,k,v; [s*B+b][H] for ctx
__device__ float g_q[B_SZ * NH * S_LEN * DH];
__device__ float g_k[B_SZ * NH * S_LEN * DH];
__device__ float g_v[B_SZ * NH * S_LEN * DH];
__device__ float g_ctx[M_ROWS * H_DIM];

// ---------------------------------------------------------------------------
// GEMM: C[M,N] = A[M,K] @ B[K,N]  (row-major). 128x128 tile, 256 threads,
// 8x8 per thread, K-tile 16.
// mode 0: QKV — add bias, scatter into q/k/v scratch
// mode 1: dense — write C directly (no bias)
// ---------------------------------------------------------------------------
__global__ __launch_bounds__(256, 2)
void gemm128(const float* __restrict__ A, const float* __restrict__ Bm,
             const float* __restrict__ bias, float* __restrict__ C,
             float* __restrict__ qd, float* __restrict__ kd, float* __restrict__ vd,
             int M, int N, int K, int mode)
{
    __shared__ float As[16][132];   // A transposed: As[k][m]
    __shared__ float Bs[16][128];   // Bs[k][n]

    const int tid = threadIdx.x;
    const int tx = tid & 15;
    const int ty = tid >> 4;
    const int m0 = blockIdx.y * 128;
    const int n0 = blockIdx.x * 128;

    float acc[8][8];
#pragma unroll
    for (int i = 0; i < 8; i++)
#pragma unroll
        for (int j = 0; j < 8; j++) acc[i][j] = 0.0f;

    const int ka = tid & 15;        // A-load k within tile
    const int ma = tid >> 4;        // A-load m base (16 per pass)
    const int kb = tid >> 5;        // B-load k base (8 rows per pass)
    const int nb = (tid & 31) << 2; // B-load n (float4)

    for (int k0 = 0; k0 < K; k0 += 16) {
#pragma unroll
        for (int p = 0; p < 8; p++) {
            int m = ma + p * 16;
            As[ka][m] = A[(size_t)(m0 + m) * K + k0 + ka];
        }
#pragma unroll
        for (int p = 0; p < 2; p++) {
            int k = kb + p * 8;
            float4 v = *reinterpret_cast<const float4*>(
                &Bm[(size_t)(k0 + k) * N + n0 + nb]);
            *reinterpret_cast<float4*>(&Bs[k][nb]) = v;
        }
        __syncthreads();

#pragma unroll
        for (int kk = 0; kk < 16; kk++) {
            float a[8], b[8];
            float4 a0 = *reinterpret_cast<const float4*>(&As[kk][ty * 8]);
            float4 a1 = *reinterpret_cast<const float4*>(&As[kk][ty * 8 + 4]);
            float4 b0 = *reinterpret_cast<const float4*>(&Bs[kk][tx * 8]);
            float4 b1 = *reinterpret_cast<const float4*>(&Bs[kk][tx * 8 + 4]);
            a[0]=a0.x; a[1]=a0.y; a[2]=a0.z; a[3]=a0.w;
            a[4]=a1.x; a[5]=a1.y; a[6]=a1.z; a[7]=a1.w;
            b[0]=b0.x; b[1]=b0.y; b[2]=b0.z; b[3]=b0.w;
            b[4]=b1.x; b[5]=b1.y; b[6]=b1.z; b[7]=b1.w;
#pragma unroll
            for (int i = 0; i < 8; i++)
#pragma unroll
                for (int j = 0; j < 8; j++)
                    acc[i][j] = fmaf(a[i], b[j], acc[i][j]);
        }
        __syncthreads();
    }

    if (mode == 0) {
        // QKV epilogue: bias + scatter into q/k/v ([b][h][s][d])
#pragma unroll
        for (int i = 0; i < 8; i++) {
            int m = m0 + ty * 8 + i;
            int b = m & 1;              // B_SZ == 2: row m = s*B + b
            int s = m >> 1;
#pragma unroll
            for (int j = 0; j < 8; j++) {
                int n = n0 + tx * 8 + j;
                float v = acc[i][j] + bias[n];
                int head = n / (3 * DH);
                int r = n - head * (3 * DH);
                int part = r >> 7;      // DH == 128
                int d = r & 127;
                size_t idx = (((size_t)(b * NH + head)) * S_LEN + s) * DH + d;
                if (part == 0)      qd[idx] = v;
                else if (part == 1) kd[idx] = v;
                else                vd[idx] = v;
            }
        }
    } else {
#pragma unroll
        for (int i = 0; i < 8; i++) {
            int m = m0 + ty * 8 + i;
#pragma unroll
            for (int j = 0; j < 8; j += 4) {
                float4 v = make_float4(acc[i][j], acc[i][j+1], acc[i][j+2], acc[i][j+3]);
                *reinterpret_cast<float4*>(&C[(size_t)m * N + n0 + tx * 8 + j]) = v;
            }
        }
    }
}

// ---------------------------------------------------------------------------
// Flash attention: one block = 64 queries of one (b,h). 256 threads.
// Online softmax over 32 key-tiles of 64. fp32 throughout.
// ---------------------------------------------------------------------------
#define ATT_SMEM_BYTES ((64*128 + 64*128 + 64*65 + 3*64) * 4)

__global__ __launch_bounds__(256, 2)
void attn_kernel(const unsigned char* __restrict__ mask,
                 const float* __restrict__ gq, const float* __restrict__ gk,
                 const float* __restrict__ gv, float* __restrict__ gctx)
{
    extern __shared__ float sm[];
    float* Qs   = sm;                       // 64 x 128
    float* KVs  = Qs + 64 * 128;            // 64 x 128 (K then V)
    float* Ps   = KVs + 64 * 128;           // 64 x 65
    float* mrow = Ps + 64 * 65;             // 64
    float* lrow = mrow + 64;                // 64
    float* arow = lrow + 64;                // 64

    const int tid = threadIdx.x;
    const int tx = tid & 15;
    const int ty = tid >> 4;
    const int bh = blockIdx.y;              // b*NH + h
    const int b  = bh / NH;
    const int h  = bh - b * NH;
    const int q0 = blockIdx.x * 64;

    const float* qp = gq + (size_t)bh * S_LEN * DH;
    const float* kp = gk + (size_t)bh * S_LEN * DH;
    const float* vp = gv + (size_t)bh * S_LEN * DH;
    const unsigned char* mp = mask + (size_t)b * S_LEN * S_LEN;

    const float inv_norm = 1.0f / sqrtf((float)H_DIM);

    // Load Q tile (2048 float4)
    for (int e = tid; e < 64 * 32; e += 256) {
        int r = e >> 5;
        int c = (e & 31) << 2;
        *reinterpret_cast<float4*>(&Qs[r * 128 + c]) =
            *reinterpret_cast<const float4*>(&qp[(size_t)(q0 + r) * 128 + c]);
    }
    if (tid < 64) { mrow[tid] = -INFINITY; lrow[tid] = 0.0f; }
    __syncthreads();

    float o[4][8];
#pragma unroll
    for (int i = 0; i < 4; i++)
#pragma unroll
        for (int j = 0; j < 8; j++) o[i][j] = 0.0f;

    const int ty4 = ty * 4;
    const int tx4 = tx * 4;
    const int tx8 = tx * 8;

    for (int kt = 0; kt < S_LEN / 64; kt++) {
        int t0 = kt * 64;
        // Load K tile
        for (int e = tid; e < 64 * 32; e += 256) {
            int r = e >> 5;
            int c = (e & 31) << 2;
            *reinterpret_cast<float4*>(&KVs[r * 128 + c]) =
                *reinterpret_cast<const float4*>(&kp[(size_t)(t0 + r) * 128 + c]);
        }
        __syncthreads();

        // Scores: 4x4 per thread over d=128
        float sacc[4][4];
#pragma unroll
        for (int i = 0; i < 4; i++)
#pragma unroll
            for (int j = 0; j < 4; j++) sacc[i][j] = 0.0f;

        for (int d = 0; d < 128; d += 4) {
            float4 qv[4], kv[4];
#pragma unroll
            for (int i = 0; i < 4; i++)
                qv[i] = *reinterpret_cast<const float4*>(&Qs[(ty4 + i) * 128 + d]);
#pragma unroll
            for (int j = 0; j < 4; j++)
                kv[j] = *reinterpret_cast<const float4*>(&KVs[(tx4 + j) * 128 + d]);
#pragma unroll
            for (int i = 0; i < 4; i++)
#pragma unroll
                for (int j = 0; j < 4; j++) {
                    sacc[i][j] = fmaf(qv[i].x, kv[j].x, sacc[i][j]);
                    sacc[i][j] = fmaf(qv[i].y, kv[j].y, sacc[i][j]);
                    sacc[i][j] = fmaf(qv[i].z, kv[j].z, sacc[i][j]);
                    sacc[i][j] = fmaf(qv[i].w, kv[j].w, sacc[i][j]);
                }
        }
        // Scale + mask, write to Ps
#pragma unroll
        for (int i = 0; i < 4; i++) {
            int rr = ty4 + i;
            const unsigned char* mr = mp + (size_t)(q0 + rr) * S_LEN + t0;
#pragma unroll
            for (int j = 0; j < 4; j++) {
                int cc = tx4 + j;
                float sv = sacc[i][j] * inv_norm;
                if (mr[cc]) sv = MASK_VALUE;
                Ps[rr * 65 + cc] = sv;
            }
        }
        __syncthreads();

        // Row-wise online softmax update
        if (tid < 64) {
            float* pr = &Ps[tid * 65];
            float rmax = pr[0];
#pragma unroll 8
            for (int c = 1; c < 64; c++) rmax = fmaxf(rmax, pr[c]);
            float m_old = mrow[tid];
            float m_new = fmaxf(m_old, rmax);
            float alpha = __expf(m_old - m_new);   // expf(-inf)=0 on first tile
            float sum = 0.0f;
#pragma unroll 8
            for (int c = 0; c < 64; c++) {
                float p = __expf(pr[c] - m_new);
                pr[c] = p;
                sum += p;
            }
            lrow[tid] = lrow[tid] * alpha + sum;
            mrow[tid] = m_new;
            arow[tid] = alpha;
        }
        __syncthreads();

        // Rescale accumulators; load V tile (overwrites K buffer)
        float al[4];
#pragma unroll
        for (int i = 0; i < 4; i++) al[i] = arow[ty4 + i];
#pragma unroll
        for (int i = 0; i < 4; i++)
#pragma unroll
            for (int j = 0; j < 8; j++) o[i][j] *= al[i];

        for (int e = tid; e < 64 * 32; e += 256) {
            int r = e >> 5;
            int c = (e & 31) << 2;
            *reinterpret_cast<float4*>(&KVs[r * 128 + c]) =
                *reinterpret_cast<const float4*>(&vp[(size_t)(t0 + r) * 128 + c]);
        }
        __syncthreads();

        // o += P @ V
        for (int t = 0; t < 64; t++) {
            float p[4];
#pragma unroll
            for (int i = 0; i < 4; i++) p[i] = Ps[(ty4 + i) * 65 + t];
            float4 v0 = *reinterpret_cast<const float4*>(&KVs[t * 128 + tx8]);
            float4 v1 = *reinterpret_cast<const float4*>(&KVs[t * 128 + tx8 + 4]);
#pragma unroll
            for (int i = 0; i < 4; i++) {
                o[i][0] = fmaf(p[i], v0.x, o[i][0]);
                o[i][1] = fmaf(p[i], v0.y, o[i][1]);
                o[i][2] = fmaf(p[i], v0.z, o[i][2]);
                o[i][3] = fmaf(p[i], v0.w, o[i][3]);
                o[i][4] = fmaf(p[i], v1.x, o[i][4]);
                o[i][5] = fmaf(p[i], v1.y, o[i][5]);
                o[i][6] = fmaf(p[i], v1.z, o[i][6]);
                o[i][7] = fmaf(p[i], v1.w, o[i][7]);
            }
        }
        __syncthreads();
    }

    // Final: o /= l, write ctx[(s*B+b)*H + h*DH + d]
#pragma unroll
    for (int i = 0; i < 4; i++) {
        int s = q0 + ty4 + i;
        float linv = 1.0f / lrow[ty4 + i];
        float* dst = &gctx[((size_t)s * B_SZ + b) * H_DIM + h * DH + tx8];
        float4 w0 = make_float4(o[i][0]*linv, o[i][1]*linv, o[i][2]*linv, o[i][3]*linv);
        float4 w1 = make_float4(o[i][4]*linv, o[i][5]*linv, o[i][6]*linv, o[i][7]*linv);
        *reinterpret_cast<float4*>(dst) = w0;
        *reinterpret_cast<float4*>(dst + 4) = w1;
    }
}

// Append b_dense after out (reference returns tuple (out, b_dense))
__global__ void tail_copy(const float* __restrict__ bd, float* __restrict__ out)
{
    int i = blockIdx.x * blockDim.x + threadIdx.x;
    if (i < H_DIM) out[(size_t)M_ROWS * H_DIM + i] = bd[i];
}

extern "C" void kernel_launch(void* const* d_in, const int* in_sizes, int n_in,
                              void* d_out, int out_size)
{
    const float* hidden = (const float*)d_in[0];
    const unsigned char* mask = (const unsigned char*)d_in[1];
    const float* W_qkv = (const float*)d_in[2];
    const float* b_qkv = (const float*)d_in[3];
    const float* W_dense = (const float*)d_in[4];
    const float* b_dense = (const float*)d_in[5];
    float* out = (float*)d_out;

    // Resolve the REAL device addresses of the __device__ scratch arrays.
    // (Passing the symbol directly from host code yields the host shadow
    //  address — with ATS on GB300 the GPU silently reads host zeros. R1 bug.)
    float *qd = nullptr, *kd = nullptr, *vd = nullptr, *ctxd = nullptr;
    cudaGetSymbolAddress((void**)&qd,   g_q);
    cudaGetSymbolAddress((void**)&kd,   g_k);
    cudaGetSymbolAddress((void**)&vd,   g_v);
    cudaGetSymbolAddress((void**)&ctxd, g_ctx);

    cudaFuncSetAttribute(attn_kernel,
                         cudaFuncAttributeMaxDynamicSharedMemorySize,
                         ATT_SMEM_BYTES);

    // 1) QKV GEMM + scatter
    {
        dim3 grid(N3 / 128, M_ROWS / 128);
        gemm128<<<grid, 256>>>(hidden, W_qkv, b_qkv, nullptr,
                               qd, kd, vd, M_ROWS, N3, H_DIM, 0);
    }
    // 2) Flash attention
    {
        dim3 grid(S_LEN / 64, B_SZ * NH);
        attn_kernel<<<grid, 256, ATT_SMEM_BYTES>>>(mask, qd, kd, vd, ctxd);
    }
    // 3) Dense GEMM -> out (no bias added, per reference)
    {
        dim3 grid(H_DIM / 128, M_ROWS / 128);
        gemm128<<<grid, 256>>>(ctxd, W_dense, nullptr, out,
                               nullptr, nullptr, nullptr, M_ROWS, H_DIM, H_DIM, 1);
    }
    // 4) Append b_dense if the output buffer includes the tuple tail
    if (out_size >= M_ROWS * H_DIM + H_DIM) {
        tail_copy<<<(H_DIM + 255) / 256, 256>>>(b_dense, out);
    }
}

// round 3
// speedup vs baseline: 1.1210x; 1.1210x over previous
#include <cuda_runtime.h>
#include <math.h>
#include <stdint.h>

// Problem constants
#define S_LEN 2048
#define B_SZ  2
#define H_DIM 2048
#define NH    16
#define DH    128
#define N3    (3 * H_DIM)          // 6144
#define M_ROWS (S_LEN * B_SZ)      // 4096
#define MASK_VALUE (-10000.0f)

// Scratch — [b][h][s][d] layout for q,k,v; [s*B+b][H] for ctx
__device__ float g_q[B_SZ * NH * S_LEN * DH];
__device__ float g_k[B_SZ * NH * S_LEN * DH];
__device__ float g_v[B_SZ * NH * S_LEN * DH];
__device__ float g_ctx[M_ROWS * H_DIM];

// ---------------------------------------------------------------------------
// Tensor-core GEMM (3xTF32 split = fp32 accuracy on tensor pipe)
// C[M,N] = A[M,K] @ B[K,N], row-major. 128x128 block tile, 256 thr (8 warps),
// warp tile 64x32 (4x4 grid of m16n8k8), BK=32.
// mode 0: QKV — add bias, scatter into q/k/v scratch
// mode 1: dense — write C directly (no bias)
// ---------------------------------------------------------------------------

__device__ __forceinline__ void split_tf32(float x, uint32_t& hi, uint32_t& lo)
{
    asm("cvt.rna.tf32.f32 %0, %1;" : "=r"(hi) : "f"(x));
    float r = x - __uint_as_float(hi);
    asm("cvt.rna.tf32.f32 %0, %1;" : "=r"(lo) : "f"(r));
}

__device__ __forceinline__ void mma_tf32(float* c, const uint32_t* a, const uint32_t* b)
{
    asm volatile(
        "mma.sync.aligned.m16n8k8.row.col.f32.tf32.tf32.f32 "
        "{%0,%1,%2,%3}, {%4,%5,%6,%7}, {%8,%9}, {%0,%1,%2,%3};"
        : "+f"(c[0]), "+f"(c[1]), "+f"(c[2]), "+f"(c[3])
        : "r"(a[0]), "r"(a[1]), "r"(a[2]), "r"(a[3]),
          "r"(b[0]), "r"(b[1]));
}

#define AS_STRIDE 36    // banks: m*36+k -> (4g+c)%32, all distinct
#define BS_STRIDE 136   // banks: k*136+n -> (8c+g)%32, all distinct

__global__ __launch_bounds__(256)
void gemm_tc(const float* __restrict__ A, const float* __restrict__ Bm,
             const float* __restrict__ bias, float* __restrict__ C,
             float* __restrict__ qd, float* __restrict__ kd, float* __restrict__ vd,
             int M, int N, int K, int mode)
{
    __shared__ float As[128][AS_STRIDE];   // [m][k]
    __shared__ float Bs[32][BS_STRIDE];    // [k][n]

    const int tid  = threadIdx.x;
    const int lane = tid & 31;
    const int warp = tid >> 5;
    const int wm   = warp & 1;             // 0..1  (64-row slabs)
    const int wn   = warp >> 1;            // 0..3  (32-col slabs)
    const int g    = lane >> 2;            // group 0..7
    const int cq   = lane & 3;             // quad  0..3

    const int m0 = blockIdx.y * 128;
    const int n0 = blockIdx.x * 128;

    float acc[4][4][4];                    // [mt][nt][frag]
#pragma unroll
    for (int mt = 0; mt < 4; mt++)
#pragma unroll
        for (int nt = 0; nt < 4; nt++)
#pragma unroll
            for (int r = 0; r < 4; r++) acc[mt][nt][r] = 0.0f;

    // global-load coordinates
    const int arow = tid >> 3;             // 0..31, 4 passes of +32
    const int akc  = (tid & 7) << 2;       // 0,4,...,28
    const int brow = tid >> 5;             // 0..7, 4 passes of +8
    const int bnc  = (tid & 31) << 2;      // 0..124

    for (int k0 = 0; k0 < K; k0 += 32) {
#pragma unroll
        for (int p = 0; p < 4; p++) {
            int m = arow + p * 32;
            float4 v = *reinterpret_cast<const float4*>(
                &A[(size_t)(m0 + m) * K + k0 + akc]);
            *reinterpret_cast<float4*>(&As[m][akc]) = v;
        }
#pragma unroll
        for (int p = 0; p < 4; p++) {
            int k = brow + p * 8;
            float4 v = *reinterpret_cast<const float4*>(
                &Bm[(size_t)(k0 + k) * N + n0 + bnc]);
            *reinterpret_cast<float4*>(&Bs[k][bnc]) = v;
        }
        __syncthreads();

#pragma unroll
        for (int kk = 0; kk < 4; kk++) {   // 4 x k8 steps
            const int kb = kk * 8;

            uint32_t ahi[4][4], alo[4][4];
#pragma unroll
            for (int mt = 0; mt < 4; mt++) {
                const int mb = wm * 64 + mt * 16;
                float a0 = As[mb + g][kb + cq];
                float a1 = As[mb + g + 8][kb + cq];
                float a2 = As[mb + g][kb + cq + 4];
                float a3 = As[mb + g + 8][kb + cq + 4];
                split_tf32(a0, ahi[mt][0], alo[mt][0]);
                split_tf32(a1, ahi[mt][1], alo[mt][1]);
                split_tf32(a2, ahi[mt][2], alo[mt][2]);
                split_tf32(a3, ahi[mt][3], alo[mt][3]);
            }
            uint32_t bhi[4][2], blo[4][2];
#pragma unroll
            for (int nt = 0; nt < 4; nt++) {
                const int nb = wn * 32 + nt * 8;
                float b0 = Bs[kb + cq][nb + g];
                float b1 = Bs[kb + cq + 4][nb + g];
                split_tf32(b0, bhi[nt][0], blo[nt][0]);
                split_tf32(b1, bhi[nt][1], blo[nt][1]);
            }
#pragma unroll
            for (int mt = 0; mt < 4; mt++)
#pragma unroll
                for (int nt = 0; nt < 4; nt++) {
                    mma_tf32(acc[mt][nt], ahi[mt], bhi[nt]);
                    mma_tf32(acc[mt][nt], ahi[mt], blo[nt]);
                    mma_tf32(acc[mt][nt], alo[mt], bhi[nt]);
                }
        }
        __syncthreads();
    }

    // Epilogue. c0:(row=g, col=2c) c1:(g,2c+1) c2:(g+8,2c) c3:(g+8,2c+1)
    if (mode == 0) {
#pragma unroll
        for (int mt = 0; mt < 4; mt++) {
#pragma unroll
            for (int nt = 0; nt < 4; nt++) {
#pragma unroll
                for (int r = 0; r < 4; r++) {
                    int m = m0 + wm * 64 + mt * 16 + g + ((r >> 1) << 3);
                    int n = n0 + wn * 32 + nt * 8 + 2 * cq + (r & 1);
                    float v = acc[mt][nt][r] + bias[n];
                    int b = m & 1;          // row m = s*B + b
                    int s = m >> 1;
                    int head = n / (3 * DH);
                    int rem  = n - head * (3 * DH);
                    int part = rem >> 7;    // DH==128
                    int d    = rem & 127;
                    size_t idx = (((size_t)(b * NH + head)) * S_LEN + s) * DH + d;
                    if (part == 0)      qd[idx] = v;
                    else if (part == 1) kd[idx] = v;
                    else                vd[idx] = v;
                }
            }
        }
    } else {
#pragma unroll
        for (int mt = 0; mt < 4; mt++) {
#pragma unroll
            for (int nt = 0; nt < 4; nt++) {
                int n = n0 + wn * 32 + nt * 8 + 2 * cq;
                int mA = m0 + wm * 64 + mt * 16 + g;
                int mB = mA + 8;
                float2 vA = make_float2(acc[mt][nt][0], acc[mt][nt][1]);
                float2 vB = make_float2(acc[mt][nt][2], acc[mt][nt][3]);
                *reinterpret_cast<float2*>(&C[(size_t)mA * N + n]) = vA;
                *reinterpret_cast<float2*>(&C[(size_t)mB * N + n]) = vB;
            }
        }
    }
}

// ---------------------------------------------------------------------------
// Flash attention: one block = 64 queries of one (b,h). 256 threads. fp32.
// ---------------------------------------------------------------------------
#define ATT_SMEM_BYTES ((64*128 + 64*128 + 64*65 + 3*64) * 4)

__global__ __launch_bounds__(256, 2)
void attn_kernel(const unsigned char* __restrict__ mask,
                 const float* __restrict__ gq, const float* __restrict__ gk,
                 const float* __restrict__ gv, float* __restrict__ gctx)
{
    extern __shared__ float sm[];
    float* Qs   = sm;                       // 64 x 128
    float* KVs  = Qs + 64 * 128;            // 64 x 128 (K then V)
    float* Ps   = KVs + 64 * 128;           // 64 x 65
    float* mrow = Ps + 64 * 65;             // 64
    float* lrow = mrow + 64;                // 64
    float* arow = lrow + 64;                // 64

    const int tid = threadIdx.x;
    const int tx = tid & 15;
    const int ty = tid >> 4;
    const int bh = blockIdx.y;              // b*NH + h
    const int b  = bh / NH;
    const int h  = bh - b * NH;
    const int q0 = blockIdx.x * 64;

    const float* qp = gq + (size_t)bh * S_LEN * DH;
    const float* kp = gk + (size_t)bh * S_LEN * DH;
    const float* vp = gv + (size_t)bh * S_LEN * DH;
    const unsigned char* mp = mask + (size_t)b * S_LEN * S_LEN;

    const float inv_norm = 1.0f / sqrtf((float)H_DIM);

    for (int e = tid; e < 64 * 32; e += 256) {
        int r = e >> 5;
        int c = (e & 31) << 2;
        *reinterpret_cast<float4*>(&Qs[r * 128 + c]) =
            *reinterpret_cast<const float4*>(&qp[(size_t)(q0 + r) * 128 + c]);
    }
    if (tid < 64) { mrow[tid] = -INFINITY; lrow[tid] = 0.0f; }
    __syncthreads();

    float o[4][8];
#pragma unroll
    for (int i = 0; i < 4; i++)
#pragma unroll
        for (int j = 0; j < 8; j++) o[i][j] = 0.0f;

    const int ty4 = ty * 4;
    const int tx4 = tx * 4;
    const int tx8 = tx * 8;

    for (int kt = 0; kt < S_LEN / 64; kt++) {
        int t0 = kt * 64;
        for (int e = tid; e < 64 * 32; e += 256) {
            int r = e >> 5;
            int c = (e & 31) << 2;
            *reinterpret_cast<float4*>(&KVs[r * 128 + c]) =
                *reinterpret_cast<const float4*>(&kp[(size_t)(t0 + r) * 128 + c]);
        }
        __syncthreads();

        float sacc[4][4];
#pragma unroll
        for (int i = 0; i < 4; i++)
#pragma unroll
            for (int j = 0; j < 4; j++) sacc[i][j] = 0.0f;

        for (int d = 0; d < 128; d += 4) {
            float4 qv[4], kv[4];
#pragma unroll
            for (int i = 0; i < 4; i++)
                qv[i] = *reinterpret_cast<const float4*>(&Qs[(ty4 + i) * 128 + d]);
#pragma unroll
            for (int j = 0; j < 4; j++)
                kv[j] = *reinterpret_cast<const float4*>(&KVs[(tx4 + j) * 128 + d]);
#pragma unroll
            for (int i = 0; i < 4; i++)
#pragma unroll
                for (int j = 0; j < 4; j++) {
                    sacc[i][j] = fmaf(qv[i].x, kv[j].x, sacc[i][j]);
                    sacc[i][j] = fmaf(qv[i].y, kv[j].y, sacc[i][j]);
                    sacc[i][j] = fmaf(qv[i].z, kv[j].z, sacc[i][j]);
                    sacc[i][j] = fmaf(qv[i].w, kv[j].w, sacc[i][j]);
                }
        }
#pragma unroll
        for (int i = 0; i < 4; i++) {
            int rr = ty4 + i;
            const unsigned char* mr = mp + (size_t)(q0 + rr) * S_LEN + t0;
#pragma unroll
            for (int j = 0; j < 4; j++) {
                int cc = tx4 + j;
                float sv = sacc[i][j] * inv_norm;
                if (mr[cc]) sv = MASK_VALUE;
                Ps[rr * 65 + cc] = sv;
            }
        }
        __syncthreads();

        if (tid < 64) {
            float* pr = &Ps[tid * 65];
            float rmax = pr[0];
#pragma unroll 8
            for (int c = 1; c < 64; c++) rmax = fmaxf(rmax, pr[c]);
            float m_old = mrow[tid];
            float m_new = fmaxf(m_old, rmax);
            float alpha = __expf(m_old - m_new);
            float sum = 0.0f;
#pragma unroll 8
            for (int c = 0; c < 64; c++) {
                float p = __expf(pr[c] - m_new);
                pr[c] = p;
                sum += p;
            }
            lrow[tid] = lrow[tid] * alpha + sum;
            mrow[tid] = m_new;
            arow[tid] = alpha;
        }
        __syncthreads();

        float al[4];
#pragma unroll
        for (int i = 0; i < 4; i++) al[i] = arow[ty4 + i];
#pragma unroll
        for (int i = 0; i < 4; i++)
#pragma unroll
            for (int j = 0; j < 8; j++) o[i][j] *= al[i];

        for (int e = tid; e < 64 * 32; e += 256) {
            int r = e >> 5;
            int c = (e & 31) << 2;
            *reinterpret_cast<float4*>(&KVs[r * 128 + c]) =
                *reinterpret_cast<const float4*>(&vp[(size_t)(t0 + r) * 128 + c]);
        }
        __syncthreads();

        for (int t = 0; t < 64; t++) {
            float p[4];
#pragma unroll
            for (int i = 0; i < 4; i++) p[i] = Ps[(ty4 + i) * 65 + t];
            float4 v0 = *reinterpret_cast<const float4*>(&KVs[t * 128 + tx8]);
            float4 v1 = *reinterpret_cast<const float4*>(&KVs[t * 128 + tx8 + 4]);
#pragma unroll
            for (int i = 0; i < 4; i++) {
                o[i][0] = fmaf(p[i], v0.x, o[i][0]);
                o[i][1] = fmaf(p[i], v0.y, o[i][1]);
                o[i][2] = fmaf(p[i], v0.z, o[i][2]);
                o[i][3] = fmaf(p[i], v0.w, o[i][3]);
                o[i][4] = fmaf(p[i], v1.x, o[i][4]);
                o[i][5] = fmaf(p[i], v1.y, o[i][5]);
                o[i][6] = fmaf(p[i], v1.z, o[i][6]);
                o[i][7] = fmaf(p[i], v1.w, o[i][7]);
            }
        }
        __syncthreads();
    }

#pragma unroll
    for (int i = 0; i < 4; i++) {
        int s = q0 + ty4 + i;
        float linv = 1.0f / lrow[ty4 + i];
        float* dst = &gctx[((size_t)s * B_SZ + b) * H_DIM + h * DH + tx8];
        float4 w0 = make_float4(o[i][0]*linv, o[i][1]*linv, o[i][2]*linv, o[i][3]*linv);
        float4 w1 = make_float4(o[i][4]*linv, o[i][5]*linv, o[i][6]*linv, o[i][7]*linv);
        *reinterpret_cast<float4*>(dst) = w0;
        *reinterpret_cast<float4*>(dst + 4) = w1;
    }
}

// Append b_dense after out (reference returns tuple (out, b_dense))
__global__ void tail_copy(const float* __restrict__ bd, float* __restrict__ out)
{
    int i = blockIdx.x * blockDim.x + threadIdx.x;
    if (i < H_DIM) out[(size_t)M_ROWS * H_DIM + i] = bd[i];
}

extern "C" void kernel_launch(void* const* d_in, const int* in_sizes, int n_in,
                              void* d_out, int out_size)
{
    const float* hidden = (const float*)d_in[0];
    const unsigned char* mask = (const unsigned char*)d_in[1];
    const float* W_qkv = (const float*)d_in[2];
    const float* b_qkv = (const float*)d_in[3];
    const float* W_dense = (const float*)d_in[4];
    const float* b_dense = (const float*)d_in[5];
    float* out = (float*)d_out;

    float *qd = nullptr, *kd = nullptr, *vd = nullptr, *ctxd = nullptr;
    cudaGetSymbolAddress((void**)&qd,   g_q);
    cudaGetSymbolAddress((void**)&kd,   g_k);
    cudaGetSymbolAddress((void**)&vd,   g_v);
    cudaGetSymbolAddress((void**)&ctxd, g_ctx);

    cudaFuncSetAttribute(attn_kernel,
                         cudaFuncAttributeMaxDynamicSharedMemorySize,
                         ATT_SMEM_BYTES);

    // 1) QKV GEMM (tensor cores) + scatter
    {
        dim3 grid(N3 / 128, M_ROWS / 128);
        gemm_tc<<<grid, 256>>>(hidden, W_qkv, b_qkv, nullptr,
                               qd, kd, vd, M_ROWS, N3, H_DIM, 0);
    }
    // 2) Flash attention (fp32 SIMT — next optimization target)
    {
        dim3 grid(S_LEN / 64, B_SZ * NH);
        attn_kernel<<<grid, 256, ATT_SMEM_BYTES>>>(mask, qd, kd, vd, ctxd);
    }
    // 3) Dense GEMM (tensor cores) -> out (no bias, per reference)
    {
        dim3 grid(H_DIM / 128, M_ROWS / 128);
        gemm_tc<<<grid, 256>>>(ctxd, W_dense, nullptr, out,
                               nullptr, nullptr, nullptr, M_ROWS, H_DIM, H_DIM, 1);
    }
    // 4) Append b_dense if the output buffer includes the tuple tail
    if (out_size >= M_ROWS * H_DIM + H_DIM) {
        tail_copy<<<(H_DIM + 255) / 256, 256>>>(b_dense, out);
    }
}

// round 4
// speedup vs baseline: 2.3178x; 2.0677x over previous
#include <cuda_runtime.h>
#include <math.h>
#include <stdint.h>

// Problem constants
#define S_LEN 2048
#define B_SZ  2
#define H_DIM 2048
#define NH    16
#define DH    128
#define N3    (3 * H_DIM)          // 6144
#define M_ROWS (S_LEN * B_SZ)      // 4096
#define MASK_VALUE (-10000.0f)

// Scratch — [b][h][s][d] layout for q,k,v; [s*B+b][H] for ctx
__device__ float g_q[B_SZ * NH * S_LEN * DH];
__device__ float g_k[B_SZ * NH * S_LEN * DH];
__device__ float g_v[B_SZ * NH * S_LEN * DH];
__device__ float g_ctx[M_ROWS * H_DIM];

// ---------------------------------------------------------------------------
// tf32 helpers
// ---------------------------------------------------------------------------
__device__ __forceinline__ void split_tf32(float x, uint32_t& hi, uint32_t& lo)
{
    asm("cvt.rna.tf32.f32 %0, %1;" : "=r"(hi) : "f"(x));
    float r = x - __uint_as_float(hi);
    asm("cvt.rna.tf32.f32 %0, %1;" : "=r"(lo) : "f"(r));
}

__device__ __forceinline__ float to_tf32(float x)
{
    uint32_t u;
    asm("cvt.rna.tf32.f32 %0, %1;" : "=r"(u) : "f"(x));
    return __uint_as_float(u);
}

__device__ __forceinline__ void mma_tf32(float* c, const uint32_t* a, const uint32_t* b)
{
    asm volatile(
        "mma.sync.aligned.m16n8k8.row.col.f32.tf32.tf32.f32 "
        "{%0,%1,%2,%3}, {%4,%5,%6,%7}, {%8,%9}, {%0,%1,%2,%3};"
        : "+f"(c[0]), "+f"(c[1]), "+f"(c[2]), "+f"(c[3])
        : "r"(a[0]), "r"(a[1]), "r"(a[2]), "r"(a[3]),
          "r"(b[0]), "r"(b[1]));
}

// ---------------------------------------------------------------------------
// Tensor-core GEMM (3xTF32, split-at-load). C[M,N] = A[M,K] @ B[K,N].
// 128x128 block tile, 256 thr (8 warps), warp tile 64x32, BK=32.
// mode 0: QKV — add bias, scatter into q/k/v scratch. mode 1: plain store.
// ---------------------------------------------------------------------------
#define AS_STRIDE 36    // a-frag banks: (4g+c)%32 distinct
#define BS_STRIDE 136   // b-frag banks: (8c+g)%32 distinct

__global__ __launch_bounds__(256)
void gemm_tc(const float* __restrict__ A, const float* __restrict__ Bm,
             const float* __restrict__ bias, float* __restrict__ C,
             float* __restrict__ qd, float* __restrict__ kd, float* __restrict__ vd,
             int M, int N, int K, int mode)
{
    __shared__ float Ahi[128][AS_STRIDE];
    __shared__ float Alo[128][AS_STRIDE];
    __shared__ float Bhi[32][BS_STRIDE];
    __shared__ float Blo[32][BS_STRIDE];

    const int tid  = threadIdx.x;
    const int lane = tid & 31;
    const int warp = tid >> 5;
    const int wm   = warp & 1;             // 64-row slabs
    const int wn   = warp >> 1;            // 32-col slabs
    const int g    = lane >> 2;
    const int cq   = lane & 3;

    const int m0 = blockIdx.y * 128;
    const int n0 = blockIdx.x * 128;

    float acc[4][4][4];
#pragma unroll
    for (int mt = 0; mt < 4; mt++)
#pragma unroll
        for (int nt = 0; nt < 4; nt++)
#pragma unroll
            for (int r = 0; r < 4; r++) acc[mt][nt][r] = 0.0f;

    const int arw = tid >> 3;              // 0..31 (+32 per pass)
    const int akc = (tid & 7) << 2;
    const int brw = tid >> 5;              // 0..7 (+8 per pass)
    const int bnc = (tid & 31) << 2;

    for (int k0 = 0; k0 < K; k0 += 32) {
#pragma unroll
        for (int p = 0; p < 4; p++) {
            int m = arw + p * 32;
            float4 v = *reinterpret_cast<const float4*>(
                &A[(size_t)(m0 + m) * K + k0 + akc]);
            uint32_t h0,l0,h1,l1,h2,l2,h3,l3;
            split_tf32(v.x, h0, l0); split_tf32(v.y, h1, l1);
            split_tf32(v.z, h2, l2); split_tf32(v.w, h3, l3);
            float4 hv = make_float4(__uint_as_float(h0), __uint_as_float(h1),
                                    __uint_as_float(h2), __uint_as_float(h3));
            float4 lv = make_float4(__uint_as_float(l0), __uint_as_float(l1),
                                    __uint_as_float(l2), __uint_as_float(l3));
            *reinterpret_cast<float4*>(&Ahi[m][akc]) = hv;
            *reinterpret_cast<float4*>(&Alo[m][akc]) = lv;
        }
#pragma unroll
        for (int p = 0; p < 4; p++) {
            int k = brw + p * 8;
            float4 v = *reinterpret_cast<const float4*>(
                &Bm[(size_t)(k0 + k) * N + n0 + bnc]);
            uint32_t h0,l0,h1,l1,h2,l2,h3,l3;
            split_tf32(v.x, h0, l0); split_tf32(v.y, h1, l1);
            split_tf32(v.z, h2, l2); split_tf32(v.w, h3, l3);
            float4 hv = make_float4(__uint_as_float(h0), __uint_as_float(h1),
                                    __uint_as_float(h2), __uint_as_float(h3));
            float4 lv = make_float4(__uint_as_float(l0), __uint_as_float(l1),
                                    __uint_as_float(l2), __uint_as_float(l3));
            *reinterpret_cast<float4*>(&Bhi[k][bnc]) = hv;
            *reinterpret_cast<float4*>(&Blo[k][bnc]) = lv;
        }
        __syncthreads();

#pragma unroll
        for (int kk = 0; kk < 4; kk++) {
            const int kb = kk * 8;
            uint32_t ah[4][4], al[4][4];
#pragma unroll
            for (int mt = 0; mt < 4; mt++) {
                const int mb = wm * 64 + mt * 16;
                ah[mt][0] = __float_as_uint(Ahi[mb + g][kb + cq]);
                ah[mt][1] = __float_as_uint(Ahi[mb + g + 8][kb + cq]);
                ah[mt][2] = __float_as_uint(Ahi[mb + g][kb + cq + 4]);
                ah[mt][3] = __float_as_uint(Ahi[mb + g + 8][kb + cq + 4]);
                al[mt][0] = __float_as_uint(Alo[mb + g][kb + cq]);
                al[mt][1] = __float_as_uint(Alo[mb + g + 8][kb + cq]);
                al[mt][2] = __float_as_uint(Alo[mb + g][kb + cq + 4]);
                al[mt][3] = __float_as_uint(Alo[mb + g + 8][kb + cq + 4]);
            }
            uint32_t bh[4][2], bl[4][2];
#pragma unroll
            for (int nt = 0; nt < 4; nt++) {
                const int nb = wn * 32 + nt * 8;
                bh[nt][0] = __float_as_uint(Bhi[kb + cq][nb + g]);
                bh[nt][1] = __float_as_uint(Bhi[kb + cq + 4][nb + g]);
                bl[nt][0] = __float_as_uint(Blo[kb + cq][nb + g]);
                bl[nt][1] = __float_as_uint(Blo[kb + cq + 4][nb + g]);
            }
#pragma unroll
            for (int mt = 0; mt < 4; mt++)
#pragma unroll
                for (int nt = 0; nt < 4; nt++) {
                    mma_tf32(acc[mt][nt], ah[mt], bh[nt]);
                    mma_tf32(acc[mt][nt], ah[mt], bl[nt]);
                    mma_tf32(acc[mt][nt], al[mt], bh[nt]);
                }
        }
        __syncthreads();
    }

    if (mode == 0) {
#pragma unroll
        for (int mt = 0; mt < 4; mt++) {
#pragma unroll
            for (int nt = 0; nt < 4; nt++) {
#pragma unroll
                for (int r = 0; r < 4; r++) {
                    int m = m0 + wm * 64 + mt * 16 + g + ((r >> 1) << 3);
                    int n = n0 + wn * 32 + nt * 8 + 2 * cq + (r & 1);
                    float v = acc[mt][nt][r] + bias[n];
                    int b = m & 1;
                    int s = m >> 1;
                    int head = n / (3 * DH);
                    int rem  = n - head * (3 * DH);
                    int part = rem >> 7;
                    int d    = rem & 127;
                    size_t idx = (((size_t)(b * NH + head)) * S_LEN + s) * DH + d;
                    if (part == 0)      qd[idx] = v;
                    else if (part == 1) kd[idx] = v;
                    else                vd[idx] = v;
                }
            }
        }
    } else {
#pragma unroll
        for (int mt = 0; mt < 4; mt++) {
#pragma unroll
            for (int nt = 0; nt < 4; nt++) {
                int n = n0 + wn * 32 + nt * 8 + 2 * cq;
                int mA = m0 + wm * 64 + mt * 16 + g;
                int mB = mA + 8;
                float2 vA = make_float2(acc[mt][nt][0], acc[mt][nt][1]);
                float2 vB = make_float2(acc[mt][nt][2], acc[mt][nt][3]);
                *reinterpret_cast<float2*>(&C[(size_t)mA * N + n]) = vA;
                *reinterpret_cast<float2*>(&C[(size_t)mB * N + n]) = vB;
            }
        }
    }
}

// ---------------------------------------------------------------------------
// Tensor-core flash attention. Block = 64 queries of one (b,h), 256 threads.
// QK^T: plain tf32 mma. P@V: 3-term tf32 split. Softmax: 4 threads/row.
// ---------------------------------------------------------------------------
#define QS_STRIDE 132
#define VS_STRIDE 136
#define PS_STRIDE 68
#define ATT_SMEM_FLOATS (64*QS_STRIDE*2 + 64*VS_STRIDE*2 + 64*PS_STRIDE*2 + 3*64)
#define ATT_SMEM_BYTES  (ATT_SMEM_FLOATS * 4)

__global__ __launch_bounds__(256)
void attn_tc(const unsigned char* __restrict__ mask,
             const float* __restrict__ gq, const float* __restrict__ gk,
             const float* __restrict__ gv, float* __restrict__ gctx)
{
    extern __shared__ float sm[];
    float* Qs   = sm;                          // 64 x 132 (tf32)
    float* Ks   = Qs  + 64 * QS_STRIDE;        // 64 x 132 (tf32)
    float* Vhi  = Ks  + 64 * QS_STRIDE;        // 64 x 136
    float* Vlo  = Vhi + 64 * VS_STRIDE;        // 64 x 136
    float* Phi  = Vlo + 64 * VS_STRIDE;        // 64 x 68
    float* Slo  = Phi + 64 * PS_STRIDE;        // 64 x 68 (raw S, then P-lo)
    float* mrow = Slo + 64 * PS_STRIDE;        // 64
    float* lrow = mrow + 64;                   // 64
    float* arow = lrow + 64;                   // 64

    const int tid  = threadIdx.x;
    const int lane = tid & 31;
    const int warp = tid >> 5;
    const int g    = lane >> 2;
    const int cq   = lane & 3;

    const int bh = blockIdx.y;
    const int b  = bh / NH;
    const int h  = bh - b * NH;
    const int q0 = blockIdx.x * 64;

    const float* qp = gq + (size_t)bh * S_LEN * DH;
    const float* kp = gk + (size_t)bh * S_LEN * DH;
    const float* vp = gv + (size_t)bh * S_LEN * DH;
    const unsigned char* mp = mask + (size_t)b * S_LEN * S_LEN;
    const float inv_norm = 1.0f / sqrtf((float)H_DIM);

    // Load Q tile (convert to tf32)
    for (int e = tid; e < 64 * 32; e += 256) {
        int r = e >> 5;
        int c = (e & 31) << 2;
        float4 q4 = *reinterpret_cast<const float4*>(&qp[(size_t)(q0 + r) * DH + c]);
        Qs[r * QS_STRIDE + c + 0] = to_tf32(q4.x);
        Qs[r * QS_STRIDE + c + 1] = to_tf32(q4.y);
        Qs[r * QS_STRIDE + c + 2] = to_tf32(q4.z);
        Qs[r * QS_STRIDE + c + 3] = to_tf32(q4.w);
    }
    if (tid < 64) { mrow[tid] = -INFINITY; lrow[tid] = 0.0f; }
    __syncthreads();

    // O accumulators: warp tile m16 x n64 (wmv row-slab, wnv 64-col slab)
    const int wmv = warp & 3;
    const int wnv = warp >> 2;
    float o[8][4];
#pragma unroll
    for (int nt = 0; nt < 8; nt++)
#pragma unroll
        for (int r = 0; r < 4; r++) o[nt][r] = 0.0f;

    // QK warp tile: m16 x n32
    const int wmq = warp & 3;
    const int wnq = warp >> 2;

    for (int kt = 0; kt < S_LEN / 64; kt++) {
        const int t0 = kt * 64;

        // Load K (tf32) and V (hi/lo split)
        for (int e = tid; e < 64 * 32; e += 256) {
            int r = e >> 5;
            int c = (e & 31) << 2;
            float4 k4 = *reinterpret_cast<const float4*>(&kp[(size_t)(t0 + r) * DH + c]);
            Ks[r * QS_STRIDE + c + 0] = to_tf32(k4.x);
            Ks[r * QS_STRIDE + c + 1] = to_tf32(k4.y);
            Ks[r * QS_STRIDE + c + 2] = to_tf32(k4.z);
            Ks[r * QS_STRIDE + c + 3] = to_tf32(k4.w);
            float4 v4 = *reinterpret_cast<const float4*>(&vp[(size_t)(t0 + r) * DH + c]);
            uint32_t h0,l0,h1,l1,h2,l2,h3,l3;
            split_tf32(v4.x, h0, l0); split_tf32(v4.y, h1, l1);
            split_tf32(v4.z, h2, l2); split_tf32(v4.w, h3, l3);
            Vhi[r * VS_STRIDE + c + 0] = __uint_as_float(h0);
            Vhi[r * VS_STRIDE + c + 1] = __uint_as_float(h1);
            Vhi[r * VS_STRIDE + c + 2] = __uint_as_float(h2);
            Vhi[r * VS_STRIDE + c + 3] = __uint_as_float(h3);
            Vlo[r * VS_STRIDE + c + 0] = __uint_as_float(l0);
            Vlo[r * VS_STRIDE + c + 1] = __uint_as_float(l1);
            Vlo[r * VS_STRIDE + c + 2] = __uint_as_float(l2);
            Vlo[r * VS_STRIDE + c + 3] = __uint_as_float(l3);
        }
        __syncthreads();

        // --- QK^T mma: S[64,64] ---
        float sacc[4][4];
#pragma unroll
        for (int nt = 0; nt < 4; nt++)
#pragma unroll
            for (int r = 0; r < 4; r++) sacc[nt][r] = 0.0f;

        const int mbq = wmq * 16;
        const int nbq = wnq * 32;
#pragma unroll
        for (int ks = 0; ks < 16; ks++) {
            const int kb = ks * 8;
            uint32_t a[4];
            a[0] = __float_as_uint(Qs[(mbq + g) * QS_STRIDE + kb + cq]);
            a[1] = __float_as_uint(Qs[(mbq + g + 8) * QS_STRIDE + kb + cq]);
            a[2] = __float_as_uint(Qs[(mbq + g) * QS_STRIDE + kb + cq + 4]);
            a[3] = __float_as_uint(Qs[(mbq + g + 8) * QS_STRIDE + kb + cq + 4]);
#pragma unroll
            for (int nt = 0; nt < 4; nt++) {
                const int nr = nbq + nt * 8 + g;
                uint32_t bfr[2];
                bfr[0] = __float_as_uint(Ks[nr * QS_STRIDE + kb + cq]);
                bfr[1] = __float_as_uint(Ks[nr * QS_STRIDE + kb + cq + 4]);
                mma_tf32(sacc[nt], a, bfr);
            }
        }
        // store raw S to Slo
#pragma unroll
        for (int nt = 0; nt < 4; nt++) {
#pragma unroll
            for (int r = 0; r < 4; r++) {
                int rr = mbq + g + ((r >> 1) << 3);
                int cc = nbq + nt * 8 + 2 * cq + (r & 1);
                Slo[rr * PS_STRIDE + cc] = sacc[nt][r];
            }
        }
        __syncthreads();

        // --- softmax: 4 threads per row ---
        {
            const int row  = tid >> 2;
            const int sub  = tid & 3;
            const int cb   = sub * 16;
            float* srow = &Slo[row * PS_STRIDE + cb];
            float* prow = &Phi[row * PS_STRIDE + cb];
            const unsigned char* mr = mp + (size_t)(q0 + row) * S_LEN + t0 + cb;

            float v[16];
            float rmax = -INFINITY;
#pragma unroll
            for (int i = 0; i < 16; i += 4) {
                uchar4 mk = *reinterpret_cast<const uchar4*>(mr + i);
                float s0 = srow[i + 0] * inv_norm; if (mk.x) s0 = MASK_VALUE;
                float s1 = srow[i + 1] * inv_norm; if (mk.y) s1 = MASK_VALUE;
                float s2 = srow[i + 2] * inv_norm; if (mk.z) s2 = MASK_VALUE;
                float s3 = srow[i + 3] * inv_norm; if (mk.w) s3 = MASK_VALUE;
                v[i + 0] = s0; v[i + 1] = s1; v[i + 2] = s2; v[i + 3] = s3;
                rmax = fmaxf(rmax, fmaxf(fmaxf(s0, s1), fmaxf(s2, s3)));
            }
            rmax = fmaxf(rmax, __shfl_xor_sync(0xffffffffu, rmax, 1));
            rmax = fmaxf(rmax, __shfl_xor_sync(0xffffffffu, rmax, 2));
            float m_old = mrow[row];
            float m_new = fmaxf(m_old, rmax);
            float alpha = __expf(m_old - m_new);
            float sum = 0.0f;
#pragma unroll
            for (int i = 0; i < 16; i++) {
                float p = __expf(v[i] - m_new);
                sum += p;
                uint32_t hi, lo;
                split_tf32(p, hi, lo);
                prow[i] = __uint_as_float(hi);
                srow[i] = __uint_as_float(lo);
            }
            sum += __shfl_xor_sync(0xffffffffu, sum, 1);
            sum += __shfl_xor_sync(0xffffffffu, sum, 2);
            if (sub == 0) {
                lrow[row] = lrow[row] * alpha + sum;
                mrow[row] = m_new;
                arow[row] = alpha;
            }
        }
        __syncthreads();

        // --- rescale O, then P@V mma ---
        const int mbv = wmv * 16;
        const int nbv = wnv * 64;
        {
            float al0 = arow[mbv + g];
            float al1 = arow[mbv + g + 8];
#pragma unroll
            for (int nt = 0; nt < 8; nt++) {
                o[nt][0] *= al0; o[nt][1] *= al0;
                o[nt][2] *= al1; o[nt][3] *= al1;
            }
        }
#pragma unroll
        for (int ks = 0; ks < 8; ks++) {
            const int kb = ks * 8;
            uint32_t ah[4], al_[4];
            ah[0]  = __float_as_uint(Phi[(mbv + g) * PS_STRIDE + kb + cq]);
            ah[1]  = __float_as_uint(Phi[(mbv + g + 8) * PS_STRIDE + kb + cq]);
            ah[2]  = __float_as_uint(Phi[(mbv + g) * PS_STRIDE + kb + cq + 4]);
            ah[3]  = __float_as_uint(Phi[(mbv + g + 8) * PS_STRIDE + kb + cq + 4]);
            al_[0] = __float_as_uint(Slo[(mbv + g) * PS_STRIDE + kb + cq]);
            al_[1] = __float_as_uint(Slo[(mbv + g + 8) * PS_STRIDE + kb + cq]);
            al_[2] = __float_as_uint(Slo[(mbv + g) * PS_STRIDE + kb + cq + 4]);
            al_[3] = __float_as_uint(Slo[(mbv + g + 8) * PS_STRIDE + kb + cq + 4]);
#pragma unroll
            for (int nt = 0; nt < 8; nt++) {
                const int nc = nbv + nt * 8 + g;
                uint32_t bhv[2], blv[2];
                bhv[0] = __float_as_uint(Vhi[(kb + cq) * VS_STRIDE + nc]);
                bhv[1] = __float_as_uint(Vhi[(kb + cq + 4) * VS_STRIDE + nc]);
                blv[0] = __float_as_uint(Vlo[(kb + cq) * VS_STRIDE + nc]);
                blv[1] = __float_as_uint(Vlo[(kb + cq + 4) * VS_STRIDE + nc]);
                mma_tf32(o[nt], ah, bhv);
                mma_tf32(o[nt], ah, blv);
                mma_tf32(o[nt], al_, bhv);
            }
        }
        __syncthreads();
    }

    // Epilogue: O /= l, write ctx
    {
        const int mbv = wmv * 16;
        const int nbv = wnv * 64;
        float li0 = 1.0f / lrow[mbv + g];
        float li1 = 1.0f / lrow[mbv + g + 8];
        int s0r = q0 + mbv + g;
        int s1r = s0r + 8;
#pragma unroll
        for (int nt = 0; nt < 8; nt++) {
            int col = h * DH + nbv + nt * 8 + 2 * cq;
            float2 w0 = make_float2(o[nt][0] * li0, o[nt][1] * li0);
            float2 w1 = make_float2(o[nt][2] * li1, o[nt][3] * li1);
            *reinterpret_cast<float2*>(&gctx[((size_t)s0r * B_SZ + b) * H_DIM + col]) = w0;
            *reinterpret_cast<float2*>(&gctx[((size_t)s1r * B_SZ + b) * H_DIM + col]) = w1;
        }
    }
}

// Append b_dense after out (reference returns tuple (out, b_dense))
__global__ void tail_copy(const float* __restrict__ bd, float* __restrict__ out)
{
    int i = blockIdx.x * blockDim.x + threadIdx.x;
    if (i < H_DIM) out[(size_t)M_ROWS * H_DIM + i] = bd[i];
}

extern "C" void kernel_launch(void* const* d_in, const int* in_sizes, int n_in,
                              void* d_out, int out_size)
{
    const float* hidden = (const float*)d_in[0];
    const unsigned char* mask = (const unsigned char*)d_in[1];
    const float* W_qkv = (const float*)d_in[2];
    const float* b_qkv = (const float*)d_in[3];
    const float* W_dense = (const float*)d_in[4];
    const float* b_dense = (const float*)d_in[5];
    float* out = (float*)d_out;

    float *qd = nullptr, *kd = nullptr, *vd = nullptr, *ctxd = nullptr;
    cudaGetSymbolAddress((void**)&qd,   g_q);
    cudaGetSymbolAddress((void**)&kd,   g_k);
    cudaGetSymbolAddress((void**)&vd,   g_v);
    cudaGetSymbolAddress((void**)&ctxd, g_ctx);

    cudaFuncSetAttribute(attn_tc,
                         cudaFuncAttributeMaxDynamicSharedMemorySize,
                         ATT_SMEM_BYTES);

    // 1) QKV GEMM (tensor cores) + scatter
    {
        dim3 grid(N3 / 128, M_ROWS / 128);
        gemm_tc<<<grid, 256>>>(hidden, W_qkv, b_qkv, nullptr,
                               qd, kd, vd, M_ROWS, N3, H_DIM, 0);
    }
    // 2) Tensor-core flash attention
    {
        dim3 grid(S_LEN / 64, B_SZ * NH);
        attn_tc<<<grid, 256, ATT_SMEM_BYTES>>>(mask, qd, kd, vd, ctxd);
    }
    // 3) Dense GEMM (tensor cores) -> out (no bias, per reference)
    {
        dim3 grid(H_DIM / 128, M_ROWS / 128);
        gemm_tc<<<grid, 256>>>(ctxd, W_dense, nullptr, out,
                               nullptr, nullptr, nullptr, M_ROWS, H_DIM, H_DIM, 1);
    }
    // 4) Append b_dense if the output buffer includes the tuple tail
    if (out_size >= M_ROWS * H_DIM + H_DIM) {
        tail_copy<<<(H_DIM + 255) / 256, 256>>>(b_dense, out);
    }
}

// round 5
// speedup vs baseline: 3.0547x; 1.3179x over previous
#include <cuda_runtime.h>
#include <cuda_bf16.h>
#include <math.h>
#include <stdint.h>

// Problem constants
#define S_LEN 2048
#define B_SZ  2
#define H_DIM 2048
#define NH    16
#define DH    128
#define N3    (3 * H_DIM)          // 6144
#define M_ROWS (S_LEN * B_SZ)      // 4096
#define MASK_VALUE (-10000.0f)

// Scratch — [b][h][s][d] layout for q,k,v; [s*B+b][H] for ctx
__device__ float g_q[B_SZ * NH * S_LEN * DH];
__device__ float g_k[B_SZ * NH * S_LEN * DH];
__device__ float g_v[B_SZ * NH * S_LEN * DH];
__device__ float g_ctx[M_ROWS * H_DIM];

// ---------------------------------------------------------------------------
// helpers
// ---------------------------------------------------------------------------
__device__ __forceinline__ float to_tf32(float x)
{
    uint32_t u;
    asm("cvt.rna.tf32.f32 %0, %1;" : "=r"(u) : "f"(x));
    return __uint_as_float(u);
}

__device__ __forceinline__ void mma_tf32(float* c, const uint32_t* a, const uint32_t* b)
{
    asm volatile(
        "mma.sync.aligned.m16n8k8.row.col.f32.tf32.tf32.f32 "
        "{%0,%1,%2,%3}, {%4,%5,%6,%7}, {%8,%9}, {%0,%1,%2,%3};"
        : "+f"(c[0]), "+f"(c[1]), "+f"(c[2]), "+f"(c[3])
        : "r"(a[0]), "r"(a[1]), "r"(a[2]), "r"(a[3]),
          "r"(b[0]), "r"(b[1]));
}

__device__ __forceinline__ void mma_bf16(float* c, const uint32_t* a, const uint32_t* b)
{
    asm volatile(
        "mma.sync.aligned.m16n8k16.row.col.f32.bf16.bf16.f32 "
        "{%0,%1,%2,%3}, {%4,%5,%6,%7}, {%8,%9}, {%0,%1,%2,%3};"
        : "+f"(c[0]), "+f"(c[1]), "+f"(c[2]), "+f"(c[3])
        : "r"(a[0]), "r"(a[1]), "r"(a[2]), "r"(a[3]),
          "r"(b[0]), "r"(b[1]));
}

// Split two floats into bf16 hi/lo pairs, packed (x0 in low half).
__device__ __forceinline__ void split2_pack(float x0, float x1,
                                            uint32_t& hi, uint32_t& lo)
{
    __nv_bfloat16 h0 = __float2bfloat16_rn(x0);
    __nv_bfloat16 h1 = __float2bfloat16_rn(x1);
    __nv_bfloat16 l0 = __float2bfloat16_rn(x0 - __bfloat162float(h0));
    __nv_bfloat16 l1 = __float2bfloat16_rn(x1 - __bfloat162float(h1));
    __nv_bfloat162 hp = __halves2bfloat162(h0, h1);
    __nv_bfloat162 lp = __halves2bfloat162(l0, l1);
    hi = *reinterpret_cast<uint32_t*>(&hp);
    lo = *reinterpret_cast<uint32_t*>(&lp);
}

// ---------------------------------------------------------------------------
// Tensor-core GEMM (3x bf16 split, packed-at-load). C[M,N] = A[M,K] @ B[K,N].
// 128x128 block tile, 256 thr (8 warps), warp tile 64x32, BK=32 (2 k16 steps).
// mode 0: QKV — add bias, scatter into q/k/v scratch. mode 1: plain store.
// ---------------------------------------------------------------------------
#define APK_STRIDE 20   // uint32 words/row (16 data + 4 pad) -> banks 20g+cq distinct
#define BPK_STRIDE 136  // banks (8cq+g) distinct

__global__ __launch_bounds__(256)
void gemm_tc(const float* __restrict__ A, const float* __restrict__ Bm,
             const float* __restrict__ bias, float* __restrict__ C,
             float* __restrict__ qd, float* __restrict__ kd, float* __restrict__ vd,
             int M, int N, int K, int mode)
{
    __shared__ uint32_t Ahi[128][APK_STRIDE];
    __shared__ uint32_t Alo[128][APK_STRIDE];
    __shared__ uint32_t Bhi[16][BPK_STRIDE];
    __shared__ uint32_t Blo[16][BPK_STRIDE];

    const int tid  = threadIdx.x;
    const int lane = tid & 31;
    const int warp = tid >> 5;
    const int wm   = warp & 1;             // 64-row slabs
    const int wn   = warp >> 1;            // 32-col slabs
    const int g    = lane >> 2;
    const int cq   = lane & 3;

    const int m0 = blockIdx.y * 128;
    const int n0 = blockIdx.x * 128;

    float acc[4][4][4];
#pragma unroll
    for (int mt = 0; mt < 4; mt++)
#pragma unroll
        for (int nt = 0; nt < 4; nt++)
#pragma unroll
            for (int r = 0; r < 4; r++) acc[mt][nt][r] = 0.0f;

    const int arw = tid >> 3;              // 0..31 (+32 per pass)
    const int akc = (tid & 7) << 2;        // k float offset (0,4,..,28)
    const int akp = (tid & 7) << 1;        // k pair-word offset
    const int bpr = tid >> 5;              // pair-row 0..7 (+8 per pass)
    const int bnc = (tid & 31) << 2;       // n offset

    for (int k0 = 0; k0 < K; k0 += 32) {
        // --- A: split+pack pairs along k ---
#pragma unroll
        for (int p = 0; p < 4; p++) {
            int m = arw + p * 32;
            float4 v = *reinterpret_cast<const float4*>(
                &A[(size_t)(m0 + m) * K + k0 + akc]);
            uint32_t h0, l0, h1, l1;
            split2_pack(v.x, v.y, h0, l0);
            split2_pack(v.z, v.w, h1, l1);
            *reinterpret_cast<uint2*>(&Ahi[m][akp]) = make_uint2(h0, h1);
            *reinterpret_cast<uint2*>(&Alo[m][akp]) = make_uint2(l0, l1);
        }
        // --- B: split+pack pairs along k (two adjacent k rows) ---
#pragma unroll
        for (int p = 0; p < 2; p++) {
            int pr = bpr + p * 8;
            const float* r0 = &Bm[(size_t)(k0 + 2 * pr) * N + n0 + bnc];
            const float* r1 = r0 + N;
            float4 u = *reinterpret_cast<const float4*>(r0);
            float4 w = *reinterpret_cast<const float4*>(r1);
            uint32_t h[4], l[4];
            split2_pack(u.x, w.x, h[0], l[0]);
            split2_pack(u.y, w.y, h[1], l[1]);
            split2_pack(u.z, w.z, h[2], l[2]);
            split2_pack(u.w, w.w, h[3], l[3]);
            *reinterpret_cast<uint4*>(&Bhi[pr][bnc]) = make_uint4(h[0], h[1], h[2], h[3]);
            *reinterpret_cast<uint4*>(&Blo[pr][bnc]) = make_uint4(l[0], l[1], l[2], l[3]);
        }
        __syncthreads();

#pragma unroll
        for (int kk = 0; kk < 2; kk++) {   // two k16 steps
            const int kb = kk * 8;         // pair-word base
            uint32_t ah[4][4], al[4][4];
#pragma unroll
            for (int mt = 0; mt < 4; mt++) {
                const int mb = wm * 64 + mt * 16;
                ah[mt][0] = Ahi[mb + g][kb + cq];
                ah[mt][1] = Ahi[mb + g + 8][kb + cq];
                ah[mt][2] = Ahi[mb + g][kb + cq + 4];
                ah[mt][3] = Ahi[mb + g + 8][kb + cq + 4];
                al[mt][0] = Alo[mb + g][kb + cq];
                al[mt][1] = Alo[mb + g + 8][kb + cq];
                al[mt][2] = Alo[mb + g][kb + cq + 4];
                al[mt][3] = Alo[mb + g + 8][kb + cq + 4];
            }
            uint32_t bh[4][2], bl[4][2];
#pragma unroll
            for (int nt = 0; nt < 4; nt++) {
                const int nb = wn * 32 + nt * 8;
                bh[nt][0] = Bhi[kb + cq][nb + g];
                bh[nt][1] = Bhi[kb + cq + 4][nb + g];
                bl[nt][0] = Blo[kb + cq][nb + g];
                bl[nt][1] = Blo[kb + cq + 4][nb + g];
            }
#pragma unroll
            for (int mt = 0; mt < 4; mt++)
#pragma unroll
                for (int nt = 0; nt < 4; nt++) {
                    mma_bf16(acc[mt][nt], ah[mt], bh[nt]);
                    mma_bf16(acc[mt][nt], ah[mt], bl[nt]);
                    mma_bf16(acc[mt][nt], al[mt], bh[nt]);
                }
        }
        __syncthreads();
    }

    if (mode == 0) {
#pragma unroll
        for (int mt = 0; mt < 4; mt++) {
#pragma unroll
            for (int nt = 0; nt < 4; nt++) {
#pragma unroll
                for (int r = 0; r < 4; r++) {
                    int m = m0 + wm * 64 + mt * 16 + g + ((r >> 1) << 3);
                    int n = n0 + wn * 32 + nt * 8 + 2 * cq + (r & 1);
                    float v = acc[mt][nt][r] + bias[n];
                    int b = m & 1;
                    int s = m >> 1;
                    int head = n / (3 * DH);
                    int rem  = n - head * (3 * DH);
                    int part = rem >> 7;
                    int d    = rem & 127;
                    size_t idx = (((size_t)(b * NH + head)) * S_LEN + s) * DH + d;
                    if (part == 0)      qd[idx] = v;
                    else if (part == 1) kd[idx] = v;
                    else                vd[idx] = v;
                }
            }
        }
    } else {
#pragma unroll
        for (int mt = 0; mt < 4; mt++) {
#pragma unroll
            for (int nt = 0; nt < 4; nt++) {
                int n = n0 + wn * 32 + nt * 8 + 2 * cq;
                int mA = m0 + wm * 64 + mt * 16 + g;
                int mB = mA + 8;
                float2 vA = make_float2(acc[mt][nt][0], acc[mt][nt][1]);
                float2 vB = make_float2(acc[mt][nt][2], acc[mt][nt][3]);
                *reinterpret_cast<float2*>(&C[(size_t)mA * N + n]) = vA;
                *reinterpret_cast<float2*>(&C[(size_t)mB * N + n]) = vB;
            }
        }
    }
}

// ---------------------------------------------------------------------------
// Tensor-core flash attention. Block = 64 queries of one (b,h), 256 threads.
// QK^T: plain tf32 mma. P@V: 3-term bf16 split (packed). Softmax 4 thr/row.
// ---------------------------------------------------------------------------
#define QS_STRIDE 132
#define VPK_STRIDE 136
#define PPK_STRIDE 36
#define SR_STRIDE 68
#define ATT_SMEM_BYTES ((64*QS_STRIDE*2 + 32*VPK_STRIDE*2 + 64*PPK_STRIDE*2 \
                         + 64*SR_STRIDE + 3*64) * 4)

__global__ __launch_bounds__(256)
void attn_tc(const unsigned char* __restrict__ mask,
             const float* __restrict__ gq, const float* __restrict__ gk,
             const float* __restrict__ gv, float* __restrict__ gctx)
{
    extern __shared__ float sm[];
    float*    Qs   = sm;                                   // 64 x 132 (tf32)
    float*    Ks   = Qs + 64 * QS_STRIDE;                  // 64 x 132 (tf32)
    uint32_t* Vhi  = reinterpret_cast<uint32_t*>(Ks + 64 * QS_STRIDE); // 32 x 136
    uint32_t* Vlo  = Vhi + 32 * VPK_STRIDE;                // 32 x 136
    uint32_t* Phi  = Vlo + 32 * VPK_STRIDE;                // 64 x 36
    uint32_t* Plo  = Phi + 64 * PPK_STRIDE;                // 64 x 36
    float*    Sraw = reinterpret_cast<float*>(Plo + 64 * PPK_STRIDE);  // 64 x 68
    float*    mrow = Sraw + 64 * SR_STRIDE;                // 64
    float*    lrow = mrow + 64;
    float*    arow = lrow + 64;

    const int tid  = threadIdx.x;
    const int lane = tid & 31;
    const int warp = tid >> 5;
    const int g    = lane >> 2;
    const int cq   = lane & 3;

    const int bh = blockIdx.y;
    const int b  = bh / NH;
    const int h  = bh - b * NH;
    const int q0 = blockIdx.x * 64;

    const float* qp = gq + (size_t)bh * S_LEN * DH;
    const float* kp = gk + (size_t)bh * S_LEN * DH;
    const float* vp = gv + (size_t)bh * S_LEN * DH;
    const unsigned char* mp = mask + (size_t)b * S_LEN * S_LEN;
    const float inv_norm = 1.0f / sqrtf((float)H_DIM);

    // Load Q tile (tf32)
    for (int e = tid; e < 64 * 32; e += 256) {
        int r = e >> 5;
        int c = (e & 31) << 2;
        float4 q4 = *reinterpret_cast<const float4*>(&qp[(size_t)(q0 + r) * DH + c]);
        Qs[r * QS_STRIDE + c + 0] = to_tf32(q4.x);
        Qs[r * QS_STRIDE + c + 1] = to_tf32(q4.y);
        Qs[r * QS_STRIDE + c + 2] = to_tf32(q4.z);
        Qs[r * QS_STRIDE + c + 3] = to_tf32(q4.w);
    }
    if (tid < 64) { mrow[tid] = -INFINITY; lrow[tid] = 0.0f; }
    __syncthreads();

    const int wmv = warp & 3;
    const int wnv = warp >> 2;
    float o[8][4];
#pragma unroll
    for (int nt = 0; nt < 8; nt++)
#pragma unroll
        for (int r = 0; r < 4; r++) o[nt][r] = 0.0f;

    const int wmq = warp & 3;
    const int wnq = warp >> 2;

    for (int kt = 0; kt < S_LEN / 64; kt++) {
        const int t0 = kt * 64;

        // K tile (tf32)
        for (int e = tid; e < 64 * 32; e += 256) {
            int r = e >> 5;
            int c = (e & 31) << 2;
            float4 k4 = *reinterpret_cast<const float4*>(&kp[(size_t)(t0 + r) * DH + c]);
            Ks[r * QS_STRIDE + c + 0] = to_tf32(k4.x);
            Ks[r * QS_STRIDE + c + 1] = to_tf32(k4.y);
            Ks[r * QS_STRIDE + c + 2] = to_tf32(k4.z);
            Ks[r * QS_STRIDE + c + 3] = to_tf32(k4.w);
        }
        // V tile: bf16 hi/lo packed pairs along seq (two adjacent seq rows)
        for (int e = tid; e < 32 * 32; e += 256) {
            int sp = e >> 5;                 // pair-row
            int c  = (e & 31) << 2;
            const float* r0 = &vp[(size_t)(t0 + 2 * sp) * DH + c];
            float4 u = *reinterpret_cast<const float4*>(r0);
            float4 w = *reinterpret_cast<const float4*>(r0 + DH);
            uint32_t hh[4], ll[4];
            split2_pack(u.x, w.x, hh[0], ll[0]);
            split2_pack(u.y, w.y, hh[1], ll[1]);
            split2_pack(u.z, w.z, hh[2], ll[2]);
            split2_pack(u.w, w.w, hh[3], ll[3]);
            *reinterpret_cast<uint4*>(&Vhi[sp * VPK_STRIDE + c]) =
                make_uint4(hh[0], hh[1], hh[2], hh[3]);
            *reinterpret_cast<uint4*>(&Vlo[sp * VPK_STRIDE + c]) =
                make_uint4(ll[0], ll[1], ll[2], ll[3]);
        }
        __syncthreads();

        // --- QK^T (tf32): S[64,64] ---
        float sacc[4][4];
#pragma unroll
        for (int nt = 0; nt < 4; nt++)
#pragma unroll
            for (int r = 0; r < 4; r++) sacc[nt][r] = 0.0f;

        const int mbq = wmq * 16;
        const int nbq = wnq * 32;
#pragma unroll
        for (int ks = 0; ks < 16; ks++) {
            const int kb = ks * 8;
            uint32_t a[4];
            a[0] = __float_as_uint(Qs[(mbq + g) * QS_STRIDE + kb + cq]);
            a[1] = __float_as_uint(Qs[(mbq + g + 8) * QS_STRIDE + kb + cq]);
            a[2] = __float_as_uint(Qs[(mbq + g) * QS_STRIDE + kb + cq + 4]);
            a[3] = __float_as_uint(Qs[(mbq + g + 8) * QS_STRIDE + kb + cq + 4]);
#pragma unroll
            for (int nt = 0; nt < 4; nt++) {
                const int nr = nbq + nt * 8 + g;
                uint32_t bfr[2];
                bfr[0] = __float_as_uint(Ks[nr * QS_STRIDE + kb + cq]);
                bfr[1] = __float_as_uint(Ks[nr * QS_STRIDE + kb + cq + 4]);
                mma_tf32(sacc[nt], a, bfr);
            }
        }
#pragma unroll
        for (int nt = 0; nt < 4; nt++) {
#pragma unroll
            for (int r = 0; r < 4; r++) {
                int rr = mbq + g + ((r >> 1) << 3);
                int cc = nbq + nt * 8 + 2 * cq + (r & 1);
                Sraw[rr * SR_STRIDE + cc] = sacc[nt][r];
            }
        }
        __syncthreads();

        // --- softmax: 4 threads per row; pack P hi/lo pairs along seq ---
        {
            const int row = tid >> 2;
            const int sub = tid & 3;
            const int cb  = sub * 16;
            float* srow = &Sraw[row * SR_STRIDE + cb];
            uint32_t* ph = &Phi[row * PPK_STRIDE + sub * 8];
            uint32_t* pl = &Plo[row * PPK_STRIDE + sub * 8];
            const unsigned char* mr = mp + (size_t)(q0 + row) * S_LEN + t0 + cb;

            float v[16];
            float rmax = -INFINITY;
#pragma unroll
            for (int i = 0; i < 16; i += 4) {
                uchar4 mk = *reinterpret_cast<const uchar4*>(mr + i);
                float s0 = srow[i + 0] * inv_norm; if (mk.x) s0 = MASK_VALUE;
                float s1 = srow[i + 1] * inv_norm; if (mk.y) s1 = MASK_VALUE;
                float s2 = srow[i + 2] * inv_norm; if (mk.z) s2 = MASK_VALUE;
                float s3 = srow[i + 3] * inv_norm; if (mk.w) s3 = MASK_VALUE;
                v[i + 0] = s0; v[i + 1] = s1; v[i + 2] = s2; v[i + 3] = s3;
                rmax = fmaxf(rmax, fmaxf(fmaxf(s0, s1), fmaxf(s2, s3)));
            }
            rmax = fmaxf(rmax, __shfl_xor_sync(0xffffffffu, rmax, 1));
            rmax = fmaxf(rmax, __shfl_xor_sync(0xffffffffu, rmax, 2));
            float m_old = mrow[row];
            float m_new = fmaxf(m_old, rmax);
            float alpha = __expf(m_old - m_new);
            float sum = 0.0f;
#pragma unroll
            for (int i = 0; i < 16; i += 2) {
                float p0 = __expf(v[i + 0] - m_new);
                float p1 = __expf(v[i + 1] - m_new);
                sum += p0 + p1;
                uint32_t hh, ll;
                split2_pack(p0, p1, hh, ll);
                ph[i >> 1] = hh;
                pl[i >> 1] = ll;
            }
            sum += __shfl_xor_sync(0xffffffffu, sum, 1);
            sum += __shfl_xor_sync(0xffffffffu, sum, 2);
            if (sub == 0) {
                lrow[row] = lrow[row] * alpha + sum;
                mrow[row] = m_new;
                arow[row] = alpha;
            }
        }
        __syncthreads();

        // --- rescale O, then P@V (bf16 3-split, 4 k16 steps) ---
        const int mbv = wmv * 16;
        const int nbv = wnv * 64;
        {
            float al0 = arow[mbv + g];
            float al1 = arow[mbv + g + 8];
#pragma unroll
            for (int nt = 0; nt < 8; nt++) {
                o[nt][0] *= al0; o[nt][1] *= al0;
                o[nt][2] *= al1; o[nt][3] *= al1;
            }
        }
#pragma unroll
        for (int ks = 0; ks < 4; ks++) {
            const int kb = ks * 8;           // pair-word base
            uint32_t ah[4], al_[4];
            ah[0]  = Phi[(mbv + g) * PPK_STRIDE + kb + cq];
            ah[1]  = Phi[(mbv + g + 8) * PPK_STRIDE + kb + cq];
            ah[2]  = Phi[(mbv + g) * PPK_STRIDE + kb + cq + 4];
            ah[3]  = Phi[(mbv + g + 8) * PPK_STRIDE + kb + cq + 4];
            al_[0] = Plo[(mbv + g) * PPK_STRIDE + kb + cq];
            al_[1] = Plo[(mbv + g + 8) * PPK_STRIDE + kb + cq];
            al_[2] = Plo[(mbv + g) * PPK_STRIDE + kb + cq + 4];
            al_[3] = Plo[(mbv + g + 8) * PPK_STRIDE + kb + cq + 4];
#pragma unroll
            for (int nt = 0; nt < 8; nt++) {
                const int nc = nbv + nt * 8 + g;
                uint32_t bhv[2], blv[2];
                bhv[0] = Vhi[(kb + cq) * VPK_STRIDE + nc];
                bhv[1] = Vhi[(kb + cq + 4) * VPK_STRIDE + nc];
                blv[0] = Vlo[(kb + cq) * VPK_STRIDE + nc];
                blv[1] = Vlo[(kb + cq + 4) * VPK_STRIDE + nc];
                mma_bf16(o[nt], ah, bhv);
                mma_bf16(o[nt], ah, blv);
                mma_bf16(o[nt], al_, bhv);
            }
        }
        __syncthreads();
    }

    // Epilogue: O /= l, write ctx
    {
        const int mbv = wmv * 16;
        const int nbv = wnv * 64;
        float li0 = 1.0f / lrow[mbv + g];
        float li1 = 1.0f / lrow[mbv + g + 8];
        int s0r = q0 + mbv + g;
        int s1r = s0r + 8;
#pragma unroll
        for (int nt = 0; nt < 8; nt++) {
            int col = h * DH + nbv + nt * 8 + 2 * cq;
            float2 w0 = make_float2(o[nt][0] * li0, o[nt][1] * li0);
            float2 w1 = make_float2(o[nt][2] * li1, o[nt][3] * li1);
            *reinterpret_cast<float2*>(&gctx[((size_t)s0r * B_SZ + b) * H_DIM + col]) = w0;
            *reinterpret_cast<float2*>(&gctx[((size_t)s1r * B_SZ + b) * H_DIM + col]) = w1;
        }
    }
}

// Append b_dense after out (reference returns tuple (out, b_dense))
__global__ void tail_copy(const float* __restrict__ bd, float* __restrict__ out)
{
    int i = blockIdx.x * blockDim.x + threadIdx.x;
    if (i < H_DIM) out[(size_t)M_ROWS * H_DIM + i] = bd[i];
}

extern "C" void kernel_launch(void* const* d_in, const int* in_sizes, int n_in,
                              void* d_out, int out_size)
{
    const float* hidden = (const float*)d_in[0];
    const unsigned char* mask = (const unsigned char*)d_in[1];
    const float* W_qkv = (const float*)d_in[2];
    const float* b_qkv = (const float*)d_in[3];
    const float* W_dense = (const float*)d_in[4];
    const float* b_dense = (const float*)d_in[5];
    float* out = (float*)d_out;

    float *qd = nullptr, *kd = nullptr, *vd = nullptr, *ctxd = nullptr;
    cudaGetSymbolAddress((void**)&qd,   g_q);
    cudaGetSymbolAddress((void**)&kd,   g_k);
    cudaGetSymbolAddress((void**)&vd,   g_v);
    cudaGetSymbolAddress((void**)&ctxd, g_ctx);

    cudaFuncSetAttribute(attn_tc,
                         cudaFuncAttributeMaxDynamicSharedMemorySize,
                         ATT_SMEM_BYTES);

    // 1) QKV GEMM (bf16-split tensor cores) + scatter
    {
        dim3 grid(N3 / 128, M_ROWS / 128);
        gemm_tc<<<grid, 256>>>(hidden, W_qkv, b_qkv, nullptr,
                               qd, kd, vd, M_ROWS, N3, H_DIM, 0);
    }
    // 2) Tensor-core flash attention
    {
        dim3 grid(S_LEN / 64, B_SZ * NH);
        attn_tc<<<grid, 256, ATT_SMEM_BYTES>>>(mask, qd, kd, vd, ctxd);
    }
    // 3) Dense GEMM -> out (no bias, per reference)
    {
        dim3 grid(H_DIM / 128, M_ROWS / 128);
        gemm_tc<<<grid, 256>>>(ctxd, W_dense, nullptr, out,
                               nullptr, nullptr, nullptr, M_ROWS, H_DIM, H_DIM, 1);
    }
    // 4) Append b_dense if the output buffer includes the tuple tail
    if (out_size >= M_ROWS * H_DIM + H_DIM) {
        tail_copy<<<(H_DIM + 255) / 256, 256>>>(b_dense, out);
    }
}